// round 10
// baseline (speedup 1.0000x reference)
#include <cuda_runtime.h>

#define N2   2048
#define NPIX (N2*N2)
#define CAP  65536
#define CW_WARPS 4096
#define RW   128
#define MARGIN 6144

// ---------------- device scratch (static allocation only) ----------------
__device__ unsigned d_keys[NPIX];        // monotonic keys        (67 MB)
__device__ float    d_cw[80];            // weff[72], beff, db (gate path)
__device__ unsigned d_hist1[4096];
__device__ unsigned d_hist2[4096];
__device__ unsigned d_sel[8];            // [0]=b1 [1]=needed1 [2]=thrKey [3]=C
__device__ unsigned d_warpCnt[CW_WARPS];
__device__ unsigned d_warpOff[CW_WARPS];
__device__ unsigned d_ci[2][CAP];        // candidate ~key (ping-pong)
__device__ unsigned d_cx[2][CAP];        // payload = candidate slot (ping-pong)
__device__ unsigned d_cpix[CAP];         // slot -> pixel idx
__device__ float    d_csym[CAP * 8];     // slot -> sym[8] (2 MB)
__device__ unsigned d_wh[RW * 256];      // radix per-warp hist
__device__ unsigned d_woff[RW * 256];    // radix per-warp scatter offsets

// ---------------- init: zero control state + combine gate weights ----------------
__global__ void k_init(const float* __restrict__ ws, const float* __restrict__ bs,
                       const float* __restrict__ w0, const float* __restrict__ b0,
                       const float* __restrict__ w1, const float* __restrict__ b1) {
    int t = blockIdx.x * 1024 + threadIdx.x;
    if (t < 4096)       d_hist1[t] = 0u;
    else if (t < 8192)  d_hist2[t - 4096] = 0u;
    else if (t < 8200)  d_sel[t - 8192] = 0u;
    if (blockIdx.x == 0) {
        __shared__ float sa[8];
        int tid = threadIdx.x;
        if (tid < 8) sa[tid] = ws[8 + tid] - ws[tid];
        __syncthreads();
        if (tid < 72) {
            float s = 0.f;
            #pragma unroll
            for (int e = 0; e < 4; e++)
                s += sa[e] * w0[e * 72 + tid] + sa[4 + e] * w1[e * 72 + tid];
            d_cw[tid] = s;
        } else if (tid == 72) {
            float s = 0.f;
            #pragma unroll
            for (int e = 0; e < 4; e++) s += sa[e] * b0[e] + sa[4 + e] * b1[e];
            d_cw[72] = s;
        } else if (tid == 73) {
            d_cw[73] = bs[1] - bs[0];
        }
    }
}

// ---------------- fused conv + symmetrize + key + hist1 (pair-tile) ----------------
// Block handles tile pair {(a,b),(b,a)}: region A rows [32a,32a+32) cols [32b,..),
// region B rows [32b,..) cols [32a,..). w(i,j)=0.5*(u(i,j)+u(j,i))+db computed
// entirely from the two u tiles in smem; both key tiles written coalesced.
__global__ __launch_bounds__(256) void k_convsym(const float* __restrict__ rel) {
    __shared__ float inA[34][36], inB[34][36];
    __shared__ float uu[2][32][33];
    __shared__ unsigned sh[4096];
    __shared__ float wsm[74];
    int tx = threadIdx.x, ty = threadIdx.y;     // 32 x 8
    int tid = ty * 32 + tx;
    for (int i = tid; i < 4096; i += 256) sh[i] = 0u;
    if (tid < 74) wsm[tid] = d_cw[tid];

    // decode triangular pair index (a <= b), 64 tile-rows
    int bid = blockIdx.x;
    int a = 0, off = 0;
    while (off + (64 - a) <= bid) { off += 64 - a; a++; }
    int b = a + (bid - off);
    int yA = a * 32, xA = b * 32;
    int yB = b * 32, xB = a * 32;
    bool diag = (a == b);

    float accA[4] = {0.f, 0.f, 0.f, 0.f};
    float accB[4] = {0.f, 0.f, 0.f, 0.f};
    for (int c = 0; c < 8; c++) {
        __syncthreads();
        const float* rc = rel + (size_t)c * NPIX;
        for (int t = tid; t < 34 * 34; t += 256) {
            int r = t / 34, cc = t - r * 34;
            int gy = yA - 1 + r, gx = xA - 1 + cc;
            inA[r][cc] = ((unsigned)gy < N2 && (unsigned)gx < N2) ? rc[gy * N2 + gx] : 0.f;
            gy = yB - 1 + r; gx = xB - 1 + cc;
            inB[r][cc] = ((unsigned)gy < N2 && (unsigned)gx < N2) ? rc[gy * N2 + gx] : 0.f;
        }
        __syncthreads();
        const float* wc = &wsm[c * 9];
        int base = ty * 4;              // 4 consecutive output rows per thread
        #pragma unroll
        for (int k = 0; k < 6; k++) {   // sliding window: 6 input rows, 3 cols
            float a0 = inA[base + k][tx], a1 = inA[base + k][tx + 1], a2 = inA[base + k][tx + 2];
            float b0v = inB[base + k][tx], b1v = inB[base + k][tx + 1], b2v = inB[base + k][tx + 2];
            #pragma unroll
            for (int dy = 0; dy < 3; dy++) {
                int rr = k - dy;
                if (rr >= 0 && rr < 4) {
                    accA[rr] += a0 * wc[dy * 3] + a1 * wc[dy * 3 + 1] + a2 * wc[dy * 3 + 2];
                    accB[rr] += b0v * wc[dy * 3] + b1v * wc[dy * 3 + 1] + b2v * wc[dy * 3 + 2];
                }
            }
        }
    }
    __syncthreads();
    float be = wsm[72], db = wsm[73];
    int base = ty * 4;
    #pragma unroll
    for (int rr = 0; rr < 4; rr++) {
        uu[0][base + rr][tx] = accA[rr] + be;
        uu[1][base + rr][tx] = accB[rr] + be;
    }
    __syncthreads();

    // region A keys: w = 0.5*(uA[r][c] + uB[c][r]) + db
    #pragma unroll
    for (int rr = 0; rr < 4; rr++) {
        int row = base + rr;
        float w = 0.5f * (uu[0][row][tx] + uu[1][tx][row]) + db;
        float m = (w > 0.f) ? w : -1e30f;
        unsigned bits = __float_as_uint(m);
        unsigned key  = ((int)bits < 0) ? ~bits : (bits | 0x80000000u);
        d_keys[(yA + row) * N2 + xA + tx] = key;
        unsigned bin = key >> 20;
        unsigned msk = __match_any_sync(0xffffffffu, bin);
        if ((int)(__ffs(msk) - 1) == tx) atomicAdd(&sh[bin], __popc(msk));
    }
    // region B keys (skip on diagonal: same pixels)
    if (!diag) {
        #pragma unroll
        for (int rr = 0; rr < 4; rr++) {
            int row = base + rr;
            float w = 0.5f * (uu[1][row][tx] + uu[0][tx][row]) + db;
            float m = (w > 0.f) ? w : -1e30f;
            unsigned bits = __float_as_uint(m);
            unsigned key  = ((int)bits < 0) ? ~bits : (bits | 0x80000000u);
            d_keys[(yB + row) * N2 + xB + tx] = key;
            unsigned bin = key >> 20;
            unsigned msk = __match_any_sync(0xffffffffu, bin);
            if ((int)(__ffs(msk) - 1) == tx) atomicAdd(&sh[bin], __popc(msk));
        }
    }
    __syncthreads();
    for (int bb = tid; bb < 4096; bb += 256) {
        unsigned c = sh[bb];
        if (c) atomicAdd(&d_hist1[bb], c);
    }
}

// ---------------- descending-cumulative threshold pick (mode 0/1) ----------------
__global__ void k_choose(int mode, unsigned Kv) {
    __shared__ unsigned ts[1024];
    const unsigned* hist = mode ? d_hist2 : d_hist1;
    int t = threadIdx.x;
    unsigned target = (mode == 0) ? Kv : d_sel[1];
    unsigned r[4]; unsigned lsum = 0;
    #pragma unroll
    for (int jj = 0; jj < 4; jj++) { r[jj] = hist[4095 - (t * 4 + jj)]; lsum += r[jj]; }
    ts[t] = lsum; __syncthreads();
    for (int off = 1; off < 1024; off <<= 1) {
        unsigned v = (t >= off) ? ts[t - off] : 0u;
        __syncthreads();
        ts[t] += v;
        __syncthreads();
    }
    unsigned run = ts[t] - lsum;
    #pragma unroll
    for (int jj = 0; jj < 4; jj++) {
        unsigned prev = run; run += r[jj];
        if (prev < target && run >= target) {
            unsigned b = 4095 - (t * 4 + jj);
            if (mode == 0) { d_sel[0] = b; d_sel[1] = target - prev; }
            else           { unsigned b1 = d_sel[0]; d_sel[2] = ((b1 << 12) | b) << 8; }
        }
    }
}

// ---------------- second-level histogram (uint4 + match-aggregated atomics) ----------------
__global__ void k_hist2() {
    unsigned b1 = d_sel[0];
    const uint4* kp = (const uint4*)d_keys;
    uint4 kv = kp[blockIdx.x * 512 + threadIdx.x];
    unsigned ks[4] = {kv.x, kv.y, kv.z, kv.w};
    int lane = threadIdx.x & 31;
    #pragma unroll
    for (int s = 0; s < 4; s++) {
        bool in = (ks[s] >> 20) == b1;
        unsigned bin = (ks[s] >> 8) & 0xFFFu;
        unsigned mv = in ? bin : (0x10000u | (unsigned)lane);   // singleton when inactive
        unsigned msk = __match_any_sync(0xffffffffu, mv);
        if (in && (int)(__ffs(msk) - 1) == lane)
            atomicAdd(&d_hist2[bin], __popc(msk));
    }
}

// ---------------- ordered compaction: count / scan / write ----------------
__global__ void k_ccount() {
    unsigned thr = d_sel[2];
    int w = blockIdx.x * 8 + (threadIdx.x >> 5);
    int lane = threadIdx.x & 31;
    const uint4* kp = (const uint4*)d_keys;
    int base = w * 256 + lane;   // uint4 units; warp covers 1024 keys
    unsigned cnt = 0;
    #pragma unroll
    for (int r = 0; r < 8; r++) {
        uint4 kv = kp[base + r * 32];
        cnt += (kv.x >= thr) + (kv.y >= thr) + (kv.z >= thr) + (kv.w >= thr);
    }
    cnt = __reduce_add_sync(0xffffffffu, cnt);
    if (lane == 0) d_warpCnt[w] = cnt;
}

__global__ void k_cscan() {
    __shared__ unsigned ts[1024];
    int t = threadIdx.x;
    unsigned r[4], l = 0;
    #pragma unroll
    for (int jj = 0; jj < 4; jj++) { r[jj] = d_warpCnt[t * 4 + jj]; l += r[jj]; }
    ts[t] = l; __syncthreads();
    for (int off = 1; off < 1024; off <<= 1) {
        unsigned v = (t >= off) ? ts[t - off] : 0u;
        __syncthreads();
        ts[t] += v;
        __syncthreads();
    }
    unsigned base = ts[t] - l;
    #pragma unroll
    for (int jj = 0; jj < 4; jj++) { d_warpOff[t * 4 + jj] = base; base += r[jj]; }
    if (t == 1023) d_sel[3] = (base > CAP) ? CAP : base;
}

__global__ void k_cwrite() {
    unsigned thr = d_sel[2];
    int w = blockIdx.x * 8 + (threadIdx.x >> 5);
    int lane = threadIdx.x & 31;
    unsigned run = d_warpOff[w];
    int base = w * 1024;
    for (int r = 0; r < 32; r++) {
        int e = base + r * 32 + lane;
        unsigned key = d_keys[e];
        bool p = key >= thr;
        unsigned mask = __ballot_sync(0xffffffffu, p);
        if (p) {
            unsigned pos = run + __popc(mask & ((1u << lane) - 1u));
            if (pos < CAP) {
                d_ci[0][pos]  = ~key;
                d_cx[0][pos]  = pos;          // payload = slot
                d_cpix[pos]   = (unsigned)e;  // slot -> pixel
            }
        }
        run += __popc(mask);
    }
}

// ---------------- reference-faithful evaluation (verified bit-exact R8/R9) ----------------
__device__ __forceinline__ float ldpix(const float* __restrict__ rel, int c, int y, int x) {
    bool ok = ((unsigned)y < N2) & ((unsigned)x < N2);
    int yy = ok ? y : 0;
    int xx = ok ? x : 0;
    float v = __ldg(&rel[(size_t)c * NPIX + yy * N2 + xx]);
    return ok ? v : 0.f;
}

__device__ __forceinline__ void faithful_eval(
    const float* __restrict__ rel,
    const float* w0s, const float* w1s,
    const float* bsm, const float* wssm, const float* bssm,
    int i, int j, float sym[8], float* l0o, float* l1o)
{
    float accA[8], accB[8];
    #pragma unroll
    for (int e = 0; e < 8; e++) { accA[e] = 0.f; accB[e] = 0.f; }
    #pragma unroll
    for (int dy = 0; dy < 3; dy++) {
        #pragma unroll
        for (int dx = 0; dx < 3; dx++) {
            int y1 = i + dy - 1, x1 = j + dx - 1;
            int y2 = j + dy - 1, x2 = i + dx - 1;
            #pragma unroll
            for (int c = 0; c < 8; c++) {
                float v1 = ldpix(rel, c, y1, x1);
                float v2 = ldpix(rel, c, y2, x2);
                int tap = (dy * 3 + dx) * 8 + c;
                #pragma unroll
                for (int e = 0; e < 4; e++) {
                    accA[e]     = fmaf(v1, w0s[e * 72 + tap], accA[e]);
                    accA[4 + e] = fmaf(v1, w1s[e * 72 + tap], accA[4 + e]);
                    accB[e]     = fmaf(v2, w0s[e * 72 + tap], accB[e]);
                    accB[4 + e] = fmaf(v2, w1s[e * 72 + tap], accB[4 + e]);
                }
            }
        }
    }
    #pragma unroll
    for (int e = 0; e < 8; e++) {
        float sA = accA[e] + bsm[e];
        float sB = accB[e] + bsm[e];
        sym[e] = (sA + sB) * 0.5f;
    }
    float l0 = 0.f, l1 = 0.f;
    #pragma unroll
    for (int e = 0; e < 8; e++) l0 = fmaf(sym[e], wssm[e], l0);
    l0 = l0 + bssm[0];
    #pragma unroll
    for (int e = 0; e < 8; e++) l1 = fmaf(sym[e], wssm[8 + e], l1);
    l1 = l1 + bssm[1];
    *l0o = l0; *l1o = l1;
}

__device__ __forceinline__ void load_weights_sw(
    const float* __restrict__ w0, const float* __restrict__ w1,
    const float* __restrict__ b0, const float* __restrict__ b1,
    const float* __restrict__ ws, const float* __restrict__ bs,
    float* w0s, float* w1s, float* bsm, float* wssm, float* bssm, int tid, int nthr)
{
    for (int t = tid; t < 288; t += nthr) {
        int e = t / 72, r = t - e * 72;
        int dyx = r >> 3, c = r & 7;
        int src = e * 72 + c * 9 + dyx;
        w0s[t] = w0[src];
        w1s[t] = w1[src];
    }
    if (tid < 4)  { bsm[tid] = b0[tid]; bsm[4 + tid] = b1[tid]; }
    if (tid >= 4 && tid < 20) wssm[tid - 4] = ws[tid - 4];
    if (tid >= 20 && tid < 22) bssm[tid - 20] = bs[tid - 20];
}

// rewrite candidate keys with exact values; store sym[8] per slot for emit
__global__ void k_refine(const float* __restrict__ rel,
                         const float* __restrict__ w0, const float* __restrict__ b0,
                         const float* __restrict__ w1, const float* __restrict__ b1,
                         const float* __restrict__ ws, const float* __restrict__ bs) {
    __shared__ float w0s[288], w1s[288], bsm[8], wssm[16], bssm[2];
    int tid = threadIdx.x;
    load_weights_sw(w0, w1, b0, b1, ws, bs, w0s, w1s, bsm, wssm, bssm, tid, 128);
    __syncthreads();
    unsigned C = d_sel[3];
    unsigned k = blockIdx.x * 128 + tid;
    if (k >= C) return;
    unsigned idx = d_cpix[k];
    int i = (int)(idx >> 11), j = (int)(idx & 2047u);
    float sym[8], l0, l1;
    faithful_eval(rel, w0s, w1s, bsm, wssm, bssm, i, j, sym, &l0, &l1);
    float v = (l1 > l0) ? (l1 - l0) : -1e30f;
    unsigned bits = __float_as_uint(v);
    unsigned key  = ((int)bits < 0) ? ~bits : (bits | 0x80000000u);
    d_ci[0][k] = ~key;
    #pragma unroll
    for (int e = 0; e < 8; e++) d_csym[k * 8 + e] = sym[e];
}

// ---------------- stable LSD radix sort (4 x 8-bit, ascending on ~key) ----------------
__global__ void k_rhist(int p, int s) {
    __shared__ unsigned sh[8][256];
    int warp = threadIdx.x >> 5, lane = threadIdx.x & 31;
    for (int d = lane; d < 256; d += 32) sh[warp][d] = 0u;
    __syncwarp();
    unsigned C = d_sel[3];
    int w = blockIdx.x * 8 + warp;
    unsigned base = (unsigned)w * 512u;
    for (int r = 0; r < 16; r++) {
        unsigned e = base + r * 32 + lane;
        if (e < C) {
            unsigned d = (d_ci[s][e] >> (p * 8)) & 255u;
            atomicAdd(&sh[warp][d], 1u);
        }
    }
    __syncwarp();
    for (int d = lane; d < 256; d += 32) d_wh[w * 256 + d] = sh[warp][d];
}

__global__ void k_rscan() {
    __shared__ unsigned ts[256];
    int t = threadIdx.x;
    unsigned tot = 0;
    for (int w = 0; w < RW; w++) tot += d_wh[w * 256 + t];
    ts[t] = tot; __syncthreads();
    for (int off = 1; off < 256; off <<= 1) {
        unsigned v = (t >= off) ? ts[t - off] : 0u;
        __syncthreads();
        ts[t] += v;
        __syncthreads();
    }
    unsigned run = ts[t] - tot;
    for (int w = 0; w < RW; w++) { d_woff[w * 256 + t] = run; run += d_wh[w * 256 + t]; }
}

__global__ void k_rscat(int p, int s) {
    __shared__ unsigned off[8][256];
    int warp = threadIdx.x >> 5, lane = threadIdx.x & 31;
    int w = blockIdx.x * 8 + warp;
    for (int d = lane; d < 256; d += 32) off[warp][d] = d_woff[w * 256 + d];
    __syncwarp();
    unsigned C = d_sel[3];
    unsigned base = (unsigned)w * 512u;
    int ds = 1 - s;
    for (int r = 0; r < 16; r++) {
        unsigned e = base + r * 32 + lane;
        bool act = (e < C);
        unsigned inv = 0, d = 0, idx = 0;
        if (act) { inv = d_ci[s][e]; idx = d_cx[s][e]; d = (inv >> (p * 8)) & 255u; }
        unsigned mv = act ? d : (0x100u | (unsigned)lane);
        unsigned mask = __match_any_sync(0xffffffffu, mv);
        unsigned rank = __popc(mask & ((1u << lane) - 1u));
        unsigned dst = 0;
        if (act) dst = off[warp][d] + rank;
        __syncwarp();
        if (act && rank == 0) off[warp][d] += __popc(mask);
        __syncwarp();
        if (act) { d_ci[ds][dst] = inv; d_cx[ds][dst] = idx; }
    }
}

// ---------------- emit: pure gather (sym precomputed in refine) ----------------
__global__ void k_emit(float* __restrict__ out, int K) {
    int k = blockIdx.x * 128 + threadIdx.x;
    if (k >= K) return;
    unsigned inv = d_ci[0][k];
    unsigned key = ~inv;
    float val = (key & 0x80000000u) ? __uint_as_float(key ^ 0x80000000u)
                                    : __uint_as_float(~key);
    unsigned slot = d_cx[0][k];
    unsigned idx  = d_cpix[slot];
    int i = (int)(idx >> 11), j = (int)(idx & 2047u);
    out[k]         = (float)i;
    out[K + k]     = (float)j;
    out[2 * K + k] = val;
    #pragma unroll
    for (int e = 0; e < 8; e++)
        out[3 * K + e * K + k] = d_csym[slot * 8 + e];
}

// ---------------- launch ----------------
extern "C" void kernel_launch(void* const* d_in, const int* in_sizes, int n_in,
                              void* d_out, int out_size) {
    const float* rel = (const float*)d_in[0];
    const float* w0  = (const float*)d_in[1];
    const float* b0  = (const float*)d_in[2];
    const float* w1  = (const float*)d_in[3];
    const float* b1  = (const float*)d_in[4];
    const float* ws  = (const float*)d_in[5];
    const float* bs  = (const float*)d_in[6];
    float* out = (float*)d_out;
    int K = out_size / 11;                    // [2,K]+[K]+[8,K] = 11K floats

    k_init<<<9, 1024>>>(ws, bs, w0, b0, w1, b1);
    k_convsym<<<2080, dim3(32, 8)>>>(rel);            // 64*65/2 tile pairs
    k_choose<<<1, 1024>>>(0, (unsigned)(K + MARGIN));
    k_hist2<<<2048, 512>>>();
    k_choose<<<1, 1024>>>(1, 0u);
    k_ccount<<<512, 256>>>();
    k_cscan<<<1, 1024>>>();
    k_cwrite<<<512, 256>>>();
    k_refine<<<(CAP + 127) / 128, 128>>>(rel, w0, b0, w1, b1, ws, bs);
    int s = 0;
    for (int p = 0; p < 4; p++) {
        k_rhist<<<16, 256>>>(p, s);
        k_rscan<<<1, 256>>>();
        k_rscat<<<16, 256>>>(p, s);
        s = 1 - s;
    }
    k_emit<<<(K + 127) / 128, 128>>>(out, K);
}